// round 13
// baseline (speedup 1.0000x reference)
#include <cuda_runtime.h>
#include <cuda_fp16.h>
#include <cstdint>

#define KTAGS 256
#define NTH   256
#define SMAX  1024
#define LN2F  0.69314718055994531f

// ET column-pair-major: d_ETp[c*128 + i] = half2( exp(T[2i][c]), exp(T[2i+1][c]) )
__device__ __half2 d_ETp[KTAGS * (KTAGS / 2)];

__global__ void crf_prep(const float* __restrict__ trans) {
    int idx = blockIdx.x * blockDim.x + threadIdx.x;
    if (idx < KTAGS * (KTAGS / 2)) {
        int c = idx >> 7, i = idx & 127;
        float lo = expf(trans[(2 * i)     * KTAGS + c]);
        float hi = expf(trans[(2 * i + 1) * KTAGS + c]);
        d_ETp[idx] = __floats2half2_rn(lo, hi);
    }
}

__device__ __forceinline__ __half2 u2h(unsigned int u) { __half2 h; *(unsigned int*)&h = u; return h; }

// One forward step with compile-time buffer parity.
// Uses/updates outer locals: ee, eraw, mskc, p, ktot.
#define STEP(PRE, PAR, T)                                                        \
{                                                                                \
    __syncthreads();                                                             \
    int tn_ = ((T) + 2 < S) ? ((T) + 2) : (S - 1);                               \
    float eraw2_ = emb[(size_t)tn_ * KTAGS + c];                                 \
    unsigned int hb_ = pzs[PRE];                                                 \
    int he_ = (int)((hb_ >> 10) & 0x1f);                                         \
    int ke_ = (he_ == 0) ? 0 : (he_ - 6);                                        \
    float sf_ = __uint_as_float((unsigned int)(127 - ke_) << 23);                \
    __half eesf_ = __float2half(ee * sf_);                                       \
    const uint4* pv_ = (const uint4*)pvec[PRE];                                  \
    uint4 s0_ = pv_[0], s1_ = pv_[1], s2_ = pv_[2], s3_ = pv_[3];                \
    __half2 a0_ = u2h(0u), a1_ = u2h(0u), a2_ = u2h(0u), a3_ = u2h(0u);          \
    __half2 a4_ = u2h(0u), a5_ = u2h(0u), a6_ = u2h(0u), a7_ = u2h(0u);          \
    _Pragma("unroll")                                                            \
    for (int k_ = 0; k_ < 32; k_ += 4) {                                         \
        uint4 n0_, n1_, n2_, n3_;                                                \
        if (k_ < 28) { n0_ = pv_[k_+4]; n1_ = pv_[k_+5];                         \
                       n2_ = pv_[k_+6]; n3_ = pv_[k_+7]; }                       \
        a0_ = __hfma2(u2h(et4[k_].x),   u2h(s0_.x), a0_);                        \
        a1_ = __hfma2(u2h(et4[k_].y),   u2h(s0_.y), a1_);                        \
        a2_ = __hfma2(u2h(et4[k_].z),   u2h(s0_.z), a2_);                        \
        a3_ = __hfma2(u2h(et4[k_].w),   u2h(s0_.w), a3_);                        \
        a4_ = __hfma2(u2h(et4[k_+1].x), u2h(s1_.x), a4_);                        \
        a5_ = __hfma2(u2h(et4[k_+1].y), u2h(s1_.y), a5_);                        \
        a6_ = __hfma2(u2h(et4[k_+1].z), u2h(s1_.z), a6_);                        \
        a7_ = __hfma2(u2h(et4[k_+1].w), u2h(s1_.w), a7_);                        \
        a0_ = __hfma2(u2h(et4[k_+2].x), u2h(s2_.x), a0_);                        \
        a1_ = __hfma2(u2h(et4[k_+2].y), u2h(s2_.y), a1_);                        \
        a2_ = __hfma2(u2h(et4[k_+2].z), u2h(s2_.z), a2_);                        \
        a3_ = __hfma2(u2h(et4[k_+2].w), u2h(s2_.w), a3_);                        \
        a4_ = __hfma2(u2h(et4[k_+3].x), u2h(s3_.x), a4_);                        \
        a5_ = __hfma2(u2h(et4[k_+3].y), u2h(s3_.y), a5_);                        \
        a6_ = __hfma2(u2h(et4[k_+3].z), u2h(s3_.z), a6_);                        \
        a7_ = __hfma2(u2h(et4[k_+3].w), u2h(s3_.w), a7_);                        \
        if (k_ < 28) { s0_ = n0_; s1_ = n1_; s2_ = n2_; s3_ = n3_; }             \
    }                                                                            \
    __half2 sT_ = __hadd2(__hadd2(__hadd2(a0_, a1_), __hadd2(a2_, a3_)),         \
                          __hadd2(__hadd2(a4_, a5_), __hadd2(a6_, a7_)));        \
    __half pn_ = __hmul(__hadd(__low2half(sT_), __high2half(sT_)), eesf_);       \
    if (mskc) { p = pn_; ktot += ke_; }                                          \
    ((__half*)pvec[PAR])[c] = p;                                                 \
    if (tid == 0) pzs[PAR] = (unsigned int)__half_as_ushort(p);                  \
    ee = __expf(eraw); eraw = eraw2_;                                            \
    mskc = ((T) + 1 < S) ? ms[(T) + 1] : 0;                                      \
}

__global__ __launch_bounds__(NTH, 1)
void crf_main(const float* __restrict__ emissions,
              const int* __restrict__ targets,
              const int* __restrict__ masks,
              const float* __restrict__ start_t,
              const float* __restrict__ end_t,
              const float* __restrict__ trans,
              float* __restrict__ out,
              int S)
{
    __shared__ __align__(16) unsigned int pvec[2][KTAGS / 2];  // p as half2, double-buffered
    __shared__ unsigned int pzs[2];                            // proxy p as raw half bits
    __shared__ float red[8];
    __shared__ float rscr[NTH], cscr[NTH];
    __shared__ float num_smem;
    __shared__ int ms[SMAX];

    const int tid = threadIdx.x, b = blockIdx.x;
    const int lane = tid & 31, wid = tid >> 5;
    const int c = tid;                                  // my output column (tag)

    const float* emb  = emissions + (size_t)b * S * KTAGS;
    const int*   tg   = targets  + (size_t)b * S;
    const int*   mrow = masks    + (size_t)b * S;

    // ---- ET column c into registers: 128 half2 as 32 uint4 ----
    uint4 et4[32];
    {
        const uint4* etg = (const uint4*)(d_ETp + (size_t)c * 128);
        #pragma unroll
        for (int k = 0; k < 32; k++) et4[k] = etg[k];
    }

    // ---- masks into SMEM ----
    for (int t = tid; t < S && t < SMAX; t += NTH) ms[t] = mrow[t];

    // ---- Numerator ----
    float npart = 0.f; int cnt = 0;
    for (int t = tid; t < S; t += NTH) {
        int m = mrow[t] != 0; cnt += m;
        if (t >= 1 && m) {
            int pv = tg[t - 1], cu = tg[t];
            npart += trans[pv * KTAGS + cu] + emb[(size_t)t * KTAGS + cu];
        }
    }
    rscr[tid] = npart; cscr[tid] = (float)cnt;
    __syncthreads();
    if (tid == 0) {
        float tot = 0.f, cc = 0.f;
        for (int i = 0; i < NTH; i++) { tot += rscr[i]; cc += cscr[i]; }
        int seq_end = (int)cc - 1; int t0 = tg[0];
        num_smem = tot + start_t[t0] + emb[t0] + end_t[tg[seq_end]];
    }

    // ---- Init (t = 0): exact max-normalization + exact mean-p proxy ----
    float s0 = start_t[c] + emb[c];
    float m = s0;
    #pragma unroll
    for (int o = 16; o > 0; o >>= 1) m = fmaxf(m, __shfl_xor_sync(0xffffffffu, m, o));
    if (lane == 0) red[wid] = m;
    __syncthreads();
    float M = red[0];
    #pragma unroll
    for (int w = 1; w < 8; w++) M = fmaxf(M, red[w]);
    float pf0 = __expf(s0 - M);
    __half p = __float2half(pf0);
    int ktot = 0;

    ((__half*)pvec[0])[c] = p;
    float psum = pf0;
    #pragma unroll
    for (int o = 16; o > 0; o >>= 1) psum += __shfl_xor_sync(0xffffffffu, psum, o);
    if (lane == 0) red[wid] = psum;
    __syncthreads();
    if (tid == 0) {
        float Sp = 0.f;
        #pragma unroll
        for (int w = 0; w < 8; w++) Sp += red[w];
        pzs[0] = (unsigned int)__half_as_ushort(__float2half(Sp * (1.0f / 256.0f)));
    }

    // emission pipeline + rolling mask
    float ee   = __expf(emb[(size_t)((1 < S) ? 1 : 0) * KTAGS + c]);
    float eraw = emb[(size_t)((2 < S) ? 2 : (S - 1)) * KTAGS + c];
    int mskc   = (1 < S) ? ms[1] : 0;

    // ---- Forward recursion: pairs of steps with compile-time parity ----
    int t = 1;
    for (; t + 1 < S; t += 2) {
        STEP(0, 1, t);
        STEP(1, 0, t + 1);
    }
    if (t < S) STEP(0, 1, t);

    // ---- Final: denominator = M + ktot*ln2 + log(Sigma p * exp(end)) ----
    float v = __half2float(p) * __expf(end_t[c]);
    #pragma unroll
    for (int o = 16; o > 0; o >>= 1) v += __shfl_xor_sync(0xffffffffu, v, o);
    if (lane == 0) red[wid] = v;
    __syncthreads();
    if (tid == 0) {
        float tot = 0.f;
        #pragma unroll
        for (int w = 0; w < 8; w++) tot += red[w];
        out[b] = num_smem - (M + (float)ktot * LN2F + __logf(tot));
    }
}

extern "C" void kernel_launch(void* const* d_in, const int* in_sizes, int n_in,
                              void* d_out, int out_size) {
    const float* emissions = (const float*)d_in[0];
    const int*   targets   = (const int*)d_in[1];
    const int*   masks     = (const int*)d_in[2];
    const float* start_t   = (const float*)d_in[3];
    const float* end_t     = (const float*)d_in[4];
    const float* trans     = (const float*)d_in[5];
    float*       out       = (float*)d_out;

    int B = out_size;
    int S = in_sizes[1] / B;

    crf_prep<<<(KTAGS * (KTAGS / 2) + 255) / 256, 256>>>(trans);
    crf_main<<<B, NTH>>>(emissions, targets, masks, start_t, end_t, trans, out, S);
}

// round 14
// speedup vs baseline: 1.0188x; 1.0188x over previous
#include <cuda_runtime.h>
#include <cuda_fp16.h>
#include <cstdint>

#define KTAGS 256
#define NTH   256
#define SMAX  1024
#define LN2F  0.69314718055994531f

// ET column-pair-major: d_ETp[c*128 + i] = half2( exp(T[2i][c]), exp(T[2i+1][c]) )
__device__ __half2 d_ETp[KTAGS * (KTAGS / 2)];

__global__ void crf_prep(const float* __restrict__ trans) {
    int idx = blockIdx.x * blockDim.x + threadIdx.x;
    if (idx < KTAGS * (KTAGS / 2)) {
        int c = idx >> 7, i = idx & 127;
        float lo = expf(trans[(2 * i)     * KTAGS + c]);
        float hi = expf(trans[(2 * i + 1) * KTAGS + c]);
        d_ETp[idx] = __floats2half2_rn(lo, hi);
    }
}

__device__ __forceinline__ __half2 u2h(unsigned int u) { __half2 h; *(unsigned int*)&h = u; return h; }

// One forward step with compile-time buffer parity. R12-style matvec body
// (loads adjacent to use; ptxas hoists them). Uses/updates: ee, eraw, mskc, p, ktot.
#define STEP(PRE, PAR, T)                                                        \
{                                                                                \
    __syncthreads();                                                             \
    int tn_ = ((T) + 2 < S) ? ((T) + 2) : (S - 1);                               \
    float eraw2_ = emb[(size_t)tn_ * KTAGS + c];                                 \
    unsigned int hb_ = pzs[PRE];                                                 \
    int he_ = (int)((hb_ >> 10) & 0x1f);                                         \
    int ke_ = (he_ == 0) ? 0 : (he_ - 6);                                        \
    float sf_ = __uint_as_float((unsigned int)(127 - ke_) << 23);                \
    __half eesf_ = __float2half(ee * sf_);                                       \
    const uint4* pv_ = (const uint4*)pvec[PRE];                                  \
    __half2 a0_, a1_, a2_, a3_, a4_, a5_, a6_, a7_;                              \
    {                                                                            \
        uint4 q0_ = pv_[0], q1_ = pv_[1];                                        \
        a0_ = __hmul2(u2h(et4[0].x), u2h(q0_.x));                                \
        a1_ = __hmul2(u2h(et4[0].y), u2h(q0_.y));                                \
        a2_ = __hmul2(u2h(et4[0].z), u2h(q0_.z));                                \
        a3_ = __hmul2(u2h(et4[0].w), u2h(q0_.w));                                \
        a4_ = __hmul2(u2h(et4[1].x), u2h(q1_.x));                                \
        a5_ = __hmul2(u2h(et4[1].y), u2h(q1_.y));                                \
        a6_ = __hmul2(u2h(et4[1].z), u2h(q1_.z));                                \
        a7_ = __hmul2(u2h(et4[1].w), u2h(q1_.w));                                \
    }                                                                            \
    _Pragma("unroll")                                                            \
    for (int k_ = 2; k_ < 32; k_ += 2) {                                         \
        uint4 q0_ = pv_[k_];                                                     \
        uint4 q1_ = pv_[k_ + 1];                                                 \
        a0_ = __hfma2(u2h(et4[k_].x),     u2h(q0_.x), a0_);                      \
        a1_ = __hfma2(u2h(et4[k_].y),     u2h(q0_.y), a1_);                      \
        a2_ = __hfma2(u2h(et4[k_].z),     u2h(q0_.z), a2_);                      \
        a3_ = __hfma2(u2h(et4[k_].w),     u2h(q0_.w), a3_);                      \
        a4_ = __hfma2(u2h(et4[k_ + 1].x), u2h(q1_.x), a4_);                      \
        a5_ = __hfma2(u2h(et4[k_ + 1].y), u2h(q1_.y), a5_);                      \
        a6_ = __hfma2(u2h(et4[k_ + 1].z), u2h(q1_.z), a6_);                      \
        a7_ = __hfma2(u2h(et4[k_ + 1].w), u2h(q1_.w), a7_);                      \
    }                                                                            \
    __half2 sT_ = __hadd2(__hadd2(__hadd2(a0_, a1_), __hadd2(a2_, a3_)),         \
                          __hadd2(__hadd2(a4_, a5_), __hadd2(a6_, a7_)));        \
    __half pn_ = __hmul(__hadd(__low2half(sT_), __high2half(sT_)), eesf_);       \
    if (mskc) { p = pn_; ktot += ke_; }                                          \
    ((__half*)pvec[PAR])[c] = p;                                                 \
    if (tid == 0) pzs[PAR] = (unsigned int)__half_as_ushort(p);                  \
    ee = __expf(eraw); eraw = eraw2_;                                            \
    mskc = ((T) + 1 < S) ? ms[(T) + 1] : 0;                                      \
}

__global__ __launch_bounds__(NTH, 1)
void crf_main(const float* __restrict__ emissions,
              const int* __restrict__ targets,
              const int* __restrict__ masks,
              const float* __restrict__ start_t,
              const float* __restrict__ end_t,
              const float* __restrict__ trans,
              float* __restrict__ out,
              int S)
{
    __shared__ __align__(16) unsigned int pvec[2][KTAGS / 2];  // p as half2, double-buffered
    __shared__ unsigned int pzs[2];                            // proxy p as raw half bits
    __shared__ float red[8];
    __shared__ float rscr[NTH], cscr[NTH];
    __shared__ float num_smem;
    __shared__ int ms[SMAX];

    const int tid = threadIdx.x, b = blockIdx.x;
    const int lane = tid & 31, wid = tid >> 5;
    const int c = tid;                                  // my output column (tag)

    const float* emb  = emissions + (size_t)b * S * KTAGS;
    const int*   tg   = targets  + (size_t)b * S;
    const int*   mrow = masks    + (size_t)b * S;

    // ---- ET column c into registers: 128 half2 as 32 uint4 ----
    uint4 et4[32];
    {
        const uint4* etg = (const uint4*)(d_ETp + (size_t)c * 128);
        #pragma unroll
        for (int k = 0; k < 32; k++) et4[k] = etg[k];
    }

    // ---- masks into SMEM ----
    for (int t = tid; t < S && t < SMAX; t += NTH) ms[t] = mrow[t];

    // ---- Numerator ----
    float npart = 0.f; int cnt = 0;
    for (int t = tid; t < S; t += NTH) {
        int m = mrow[t] != 0; cnt += m;
        if (t >= 1 && m) {
            int pv = tg[t - 1], cu = tg[t];
            npart += trans[pv * KTAGS + cu] + emb[(size_t)t * KTAGS + cu];
        }
    }
    rscr[tid] = npart; cscr[tid] = (float)cnt;
    __syncthreads();
    if (tid == 0) {
        float tot = 0.f, cc = 0.f;
        for (int i = 0; i < NTH; i++) { tot += rscr[i]; cc += cscr[i]; }
        int seq_end = (int)cc - 1; int t0 = tg[0];
        num_smem = tot + start_t[t0] + emb[t0] + end_t[tg[seq_end]];
    }

    // ---- Init (t = 0): exact max-normalization + exact mean-p proxy ----
    float s0 = start_t[c] + emb[c];
    float m = s0;
    #pragma unroll
    for (int o = 16; o > 0; o >>= 1) m = fmaxf(m, __shfl_xor_sync(0xffffffffu, m, o));
    if (lane == 0) red[wid] = m;
    __syncthreads();
    float M = red[0];
    #pragma unroll
    for (int w = 1; w < 8; w++) M = fmaxf(M, red[w]);
    float pf0 = __expf(s0 - M);
    __half p = __float2half(pf0);
    int ktot = 0;

    ((__half*)pvec[0])[c] = p;
    float psum = pf0;
    #pragma unroll
    for (int o = 16; o > 0; o >>= 1) psum += __shfl_xor_sync(0xffffffffu, psum, o);
    if (lane == 0) red[wid] = psum;
    __syncthreads();
    if (tid == 0) {
        float Sp = 0.f;
        #pragma unroll
        for (int w = 0; w < 8; w++) Sp += red[w];
        pzs[0] = (unsigned int)__half_as_ushort(__float2half(Sp * (1.0f / 256.0f)));
    }

    // emission pipeline + rolling mask
    float ee   = __expf(emb[(size_t)((1 < S) ? 1 : 0) * KTAGS + c]);
    float eraw = emb[(size_t)((2 < S) ? 2 : (S - 1)) * KTAGS + c];
    int mskc   = (1 < S) ? ms[1] : 0;

    // ---- Forward recursion: pairs of steps with compile-time parity ----
    int t = 1;
    for (; t + 1 < S; t += 2) {
        STEP(0, 1, t);
        STEP(1, 0, t + 1);
    }
    if (t < S) STEP(0, 1, t);

    // ---- Final: denominator = M + ktot*ln2 + log(Sigma p * exp(end)) ----
    float v = __half2float(p) * __expf(end_t[c]);
    #pragma unroll
    for (int o = 16; o > 0; o >>= 1) v += __shfl_xor_sync(0xffffffffu, v, o);
    if (lane == 0) red[wid] = v;
    __syncthreads();
    if (tid == 0) {
        float tot = 0.f;
        #pragma unroll
        for (int w = 0; w < 8; w++) tot += red[w];
        out[b] = num_smem - (M + (float)ktot * LN2F + __logf(tot));
    }
}

extern "C" void kernel_launch(void* const* d_in, const int* in_sizes, int n_in,
                              void* d_out, int out_size) {
    const float* emissions = (const float*)d_in[0];
    const int*   targets   = (const int*)d_in[1];
    const int*   masks     = (const int*)d_in[2];
    const float* start_t   = (const float*)d_in[3];
    const float* end_t     = (const float*)d_in[4];
    const float* trans     = (const float*)d_in[5];
    float*       out       = (float*)d_out;

    int B = out_size;
    int S = in_sizes[1] / B;

    crf_prep<<<(KTAGS * (KTAGS / 2) + 255) / 256, 256>>>(trans);
    crf_main<<<B, NTH>>>(emissions, targets, masks, start_t, end_t, trans, out, S);
}

// round 15
// speedup vs baseline: 1.2182x; 1.1957x over previous
#include <cuda_runtime.h>
#include <cuda_fp16.h>
#include <cstdint>

#define KTAGS 256
#define NTH   256
#define SMAX  1024
#define LN2F  0.69314718055994531f

// ET column-pair-major: d_ETp[c*128 + i] = half2( exp(T[2i][c]), exp(T[2i+1][c]) )
__device__ __half2 d_ETp[KTAGS * (KTAGS / 2)];

__global__ void crf_prep(const float* __restrict__ trans) {
    int idx = blockIdx.x * blockDim.x + threadIdx.x;
    if (idx < KTAGS * (KTAGS / 2)) {
        int c = idx >> 7, i = idx & 127;
        float lo = expf(trans[(2 * i)     * KTAGS + c]);
        float hi = expf(trans[(2 * i + 1) * KTAGS + c]);
        d_ETp[idx] = __floats2half2_rn(lo, hi);
    }
}

__device__ __forceinline__ __half2 u2h(unsigned int u) { __half2 h; *(unsigned int*)&h = u; return h; }

__global__ __launch_bounds__(NTH, 1)
void crf_main(const float* __restrict__ emissions,
              const int* __restrict__ targets,
              const int* __restrict__ masks,
              const float* __restrict__ start_t,
              const float* __restrict__ end_t,
              const float* __restrict__ trans,
              float* __restrict__ out,
              int S)
{
    __shared__ __align__(16) unsigned int pvec[2][KTAGS / 2];  // p as half2, double-buffered
    __shared__ unsigned int pzs[2];                            // proxy p as raw half bits
    __shared__ float red[8];
    __shared__ float rscr[NTH], cscr[NTH];
    __shared__ float num_smem;
    __shared__ int ms[SMAX];

    const int tid = threadIdx.x, b = blockIdx.x;
    const int lane = tid & 31, wid = tid >> 5;
    const int c = tid;                                  // my output column (tag)

    const float* emb  = emissions + (size_t)b * S * KTAGS;
    const int*   tg   = targets  + (size_t)b * S;
    const int*   mrow = masks    + (size_t)b * S;

    // ---- ET column c into registers: 128 half2 as 32 uint4 ----
    uint4 et4[32];
    {
        const uint4* etg = (const uint4*)(d_ETp + (size_t)c * 128);
        #pragma unroll
        for (int k = 0; k < 32; k++) et4[k] = etg[k];
    }

    // ---- masks into SMEM ----
    for (int t = tid; t < S && t < SMAX; t += NTH) ms[t] = mrow[t];

    // ---- Numerator ----
    float npart = 0.f; int cnt = 0;
    for (int t = tid; t < S; t += NTH) {
        int m = mrow[t] != 0; cnt += m;
        if (t >= 1 && m) {
            int pv = tg[t - 1], cu = tg[t];
            npart += trans[pv * KTAGS + cu] + emb[(size_t)t * KTAGS + cu];
        }
    }
    rscr[tid] = npart; cscr[tid] = (float)cnt;
    __syncthreads();
    if (tid == 0) {
        float tot = 0.f, cc = 0.f;
        for (int i = 0; i < NTH; i++) { tot += rscr[i]; cc += cscr[i]; }
        int seq_end = (int)cc - 1; int t0 = tg[0];
        num_smem = tot + start_t[t0] + emb[t0] + end_t[tg[seq_end]];
    }

    // ---- Init (t = 0): exact max-normalization + exact mean-p proxy ----
    float s0 = start_t[c] + emb[c];
    float m = s0;
    #pragma unroll
    for (int o = 16; o > 0; o >>= 1) m = fmaxf(m, __shfl_xor_sync(0xffffffffu, m, o));
    if (lane == 0) red[wid] = m;
    __syncthreads();
    float M = red[0];
    #pragma unroll
    for (int w = 1; w < 8; w++) M = fmaxf(M, red[w]);
    float pf0 = __expf(s0 - M);
    __half p = __float2half(pf0);
    int ktot = 0;

    ((__half*)pvec[0])[c] = p;
    float psum = pf0;
    #pragma unroll
    for (int o = 16; o > 0; o >>= 1) psum += __shfl_xor_sync(0xffffffffu, psum, o);
    if (lane == 0) red[wid] = psum;
    __syncthreads();
    if (tid == 0) {
        float Sp = 0.f;
        #pragma unroll
        for (int w = 0; w < 8; w++) Sp += red[w];
        pzs[0] = (unsigned int)__half_as_ushort(__float2half(Sp * (1.0f / 256.0f)));
    }

    // emission pipeline + rolling mask
    float ee   = __expf(emb[(size_t)((1 < S) ? 1 : 0) * KTAGS + c]);
    float eraw = emb[(size_t)((2 < S) ? 2 : (S - 1)) * KTAGS + c];
    int mskc   = (1 < S) ? ms[1] : 0;

    // read/write buffer pointers (swapped each step; replaces parity selects)
    const uint4*  pv_r = (const uint4*)pvec[0];
    __half*       pv_w = (__half*)pvec[1];
    unsigned int* pz_r = &pzs[0];
    unsigned int* pz_w = &pzs[1];

    // ---- Forward recursion: one barrier per step, body kept L0-resident ----
    #pragma unroll 1
    for (int t = 1; t < S; t++) {
        __syncthreads();

        int tn = (t + 2 < S) ? (t + 2) : (S - 1);
        float eraw2 = emb[(size_t)tn * KTAGS + c];

        // lag-1 proxy normalizer from half exponent bits (subnormal-safe)
        unsigned int hb = *pz_r;
        int he = (int)((hb >> 10) & 0x1f);
        int ke = (he == 0) ? 0 : (he - 6);              // ilogb+9 in half domain
        float sf = __uint_as_float((unsigned int)(127 - ke) << 23);   // 2^-ke
        __half eesf = __float2half(ee * sf);            // folded emission*scale

        // matvec: ssum_c = sum_i p_i * ET[i][c], 8 independent fp16 chains
        __half2 a0, a1, a2, a3, a4, a5, a6, a7;
        {
            uint4 q0 = pv_r[0], q1 = pv_r[1];
            a0 = __hmul2(u2h(et4[0].x), u2h(q0.x));
            a1 = __hmul2(u2h(et4[0].y), u2h(q0.y));
            a2 = __hmul2(u2h(et4[0].z), u2h(q0.z));
            a3 = __hmul2(u2h(et4[0].w), u2h(q0.w));
            a4 = __hmul2(u2h(et4[1].x), u2h(q1.x));
            a5 = __hmul2(u2h(et4[1].y), u2h(q1.y));
            a6 = __hmul2(u2h(et4[1].z), u2h(q1.z));
            a7 = __hmul2(u2h(et4[1].w), u2h(q1.w));
        }
        #pragma unroll
        for (int k = 2; k < 32; k += 2) {
            uint4 q0 = pv_r[k];
            uint4 q1 = pv_r[k + 1];
            a0 = __hfma2(u2h(et4[k].x),     u2h(q0.x), a0);
            a1 = __hfma2(u2h(et4[k].y),     u2h(q0.y), a1);
            a2 = __hfma2(u2h(et4[k].z),     u2h(q0.z), a2);
            a3 = __hfma2(u2h(et4[k].w),     u2h(q0.w), a3);
            a4 = __hfma2(u2h(et4[k + 1].x), u2h(q1.x), a4);
            a5 = __hfma2(u2h(et4[k + 1].y), u2h(q1.y), a5);
            a6 = __hfma2(u2h(et4[k + 1].z), u2h(q1.z), a6);
            a7 = __hfma2(u2h(et4[k + 1].w), u2h(q1.w), a7);
        }
        // tail, fully in half: fold -> HADD -> HMUL(eesf) -> select -> STS.16
        __half2 sT = __hadd2(__hadd2(__hadd2(a0, a1), __hadd2(a2, a3)),
                             __hadd2(__hadd2(a4, a5), __hadd2(a6, a7)));
        __half pn = __hmul(__hadd(__low2half(sT), __high2half(sT)), eesf);
        if (mskc) { p = pn; ktot += ke; }

        pv_w[c] = p;
        if (tid == 0) *pz_w = (unsigned int)__half_as_ushort(p);

        // off-critical-path: emission exp + rolling mask for step t+1
        ee = __expf(eraw);
        eraw = eraw2;
        mskc = (t + 1 < S) ? ms[t + 1] : 0;

        // swap read/write buffers
        const uint4* tp = pv_r; pv_r = (const uint4*)pv_w; pv_w = (__half*)tp;
        unsigned int* tz = pz_r; pz_r = pz_w; pz_w = tz;
    }

    // ---- Final: denominator = M + ktot*ln2 + log(Sigma p * exp(end)) ----
    float v = __half2float(p) * __expf(end_t[c]);
    #pragma unroll
    for (int o = 16; o > 0; o >>= 1) v += __shfl_xor_sync(0xffffffffu, v, o);
    if (lane == 0) red[wid] = v;
    __syncthreads();
    if (tid == 0) {
        float tot = 0.f;
        #pragma unroll
        for (int w = 0; w < 8; w++) tot += red[w];
        out[b] = num_smem - (M + (float)ktot * LN2F + __logf(tot));
    }
}

extern "C" void kernel_launch(void* const* d_in, const int* in_sizes, int n_in,
                              void* d_out, int out_size) {
    const float* emissions = (const float*)d_in[0];
    const int*   targets   = (const int*)d_in[1];
    const int*   masks     = (const int*)d_in[2];
    const float* start_t   = (const float*)d_in[3];
    const float* end_t     = (const float*)d_in[4];
    const float* trans     = (const float*)d_in[5];
    float*       out       = (float*)d_out;

    int B = out_size;
    int S = in_sizes[1] / B;

    crf_prep<<<(KTAGS * (KTAGS / 2) + 255) / 256, 256>>>(trans);
    crf_main<<<B, NTH>>>(emissions, targets, masks, start_t, end_t, trans, out, S);
}